// round 3
// baseline (speedup 1.0000x reference)
#include <cuda_runtime.h>
#include <cuda_bf16.h>
#include <math.h>

// ---------------------------------------------------------------------------
// WReN forward: loss + accuracy.
// Shapes: B=512, slots=16 (8 ctx + 8 ans), D=512, d=D+9=521, T=2d=1042.
// Padded dims: d -> 544 (K pad), T -> 1056 (K pad), N-grid -> 1152 (9*128).
// All pads are zero-filled so they contribute nothing.
// ---------------------------------------------------------------------------

#define BATCH      512
#define SLOTS      16
#define NROWS_EMB  (BATCH * SLOTS)        // 8192
#define D_EMB      512
#define D_TAG      521
#define KP1        544                    // padded d (layer-1 K)
#define T_DIM      1042
#define KP2        1056                   // padded T (layer-2/3/f K)
#define NP         1152                   // padded N (9 * 128 tiles)
#define NP4        (NP / 4)               // 288 float4 per row
#define NV4        (KP2 / 4)              // 264 valid float4 per row
#define H_ROWS     65536                  // 32768 ctx-pairs + 32768 cc-pairs

// ------------------------- scratch (device globals) ------------------------
__device__ float g_tagged[NROWS_EMB * KP1];     // (8192, 544)  emb + tags
__device__ float g_W1top[KP1 * NP];             // Wg1[:521] padded
__device__ float g_W1bot[KP1 * NP];             // Wg1[521:] padded
__device__ float g_W2p[KP2 * NP];
__device__ float g_W3p[KP2 * NP];
__device__ float g_Wf1p[KP2 * NP];
__device__ float g_bg1p[NP];
__device__ float g_bg2p[NP];
__device__ float g_bg3p[NP];
__device__ float g_bf1p[NP];
__device__ float g_Atop[NROWS_EMB * NP];        // tagged @ W1top
__device__ float g_Bbot[NROWS_EMB * NP];        // tagged @ W1bot
__device__ float g_HA[(size_t)H_ROWS * NP];     // H1 / H3
__device__ float g_HB[(size_t)H_ROWS * NP];     // H2
__device__ float g_ctxsum[BATCH * NP];
__device__ float g_rel[BATCH * 8 * NP];
__device__ float g_H4[BATCH * 8 * NP];
__device__ float g_fout[BATCH * 8];

// ------------------------------- prep kernels ------------------------------
__global__ void pad_weight_kernel(float* __restrict__ dst,
                                  const float* __restrict__ src,
                                  int dstK, int validK, int rowOff) {
    long idx = (long)blockIdx.x * blockDim.x + threadIdx.x;
    long total = (long)dstK * NP;
    if (idx >= total) return;
    int k = (int)(idx / NP);
    int n = (int)(idx % NP);
    float v = 0.f;
    if (k < validK && n < T_DIM)
        v = src[(long)(rowOff + k) * T_DIM + n];
    dst[idx] = v;
}

__global__ void pad_bias_kernel(float* __restrict__ dst,
                                const float* __restrict__ src) {
    int n = blockIdx.x * blockDim.x + threadIdx.x;
    if (n >= NP) return;
    dst[n] = (n < T_DIM) ? src[n] : 0.f;
}

// tags: cols [512..543] of tagged. slot<8 -> eye9[slot], slot>=8 -> eye9[8].
__global__ void tag_kernel(float* __restrict__ tagged) {
    int row = blockIdx.x;          // 0..8191
    int c = threadIdx.x;           // 0..31
    int slot = row & 15;
    int tagidx = (slot < 8) ? slot : 8;
    float v = (c < 9 && c == tagidx) ? 1.f : 0.f;
    tagged[(size_t)row * KP1 + D_EMB + c] = v;
}

// ------------------------------- SGEMM -------------------------------------
// C[M,N] = op(A[M,K] * B[K,N] + bias), 128x128x16 tiles, 8x8 per thread.
// Requires: M%128==0, gridDim.x*128 == padded N, K%16==0, all ld%4==0,
// A/B/C 16B aligned at every float4 access (guaranteed by our layouts).
__global__ void __launch_bounds__(256, 2)
sgemm_kernel(const float* __restrict__ A, int lda,
             const float* __restrict__ B, int ldb,
             float* __restrict__ C, int ldc,
             int K, const float* __restrict__ bias, int doRelu) {
    __shared__ float As[16][132];   // +4 pad: conflict-free transposed stores
    __shared__ float Bs[16][128];

    const int tid = threadIdx.x;
    const int tx  = tid & 15;
    const int ty  = tid >> 4;
    const long bm = (long)blockIdx.y * 128;
    const long bn = (long)blockIdx.x * 128;

    const int aRow = tid >> 2;          // 0..63
    const int aCol = (tid & 3) << 2;    // 0,4,8,12
    const int bRow = tid >> 5;          // 0..7
    const int bCol = (tid & 31) << 2;   // 0..124

    const float* Ab0 = A + (bm + aRow) * (long)lda + aCol;
    const float* Ab1 = Ab0 + 64L * lda;
    const float* Bb0 = B + (long)bRow * ldb + bn + bCol;
    const float* Bb1 = Bb0 + 8L * ldb;

    float4 pa0 = *(const float4*)(Ab0);
    float4 pa1 = *(const float4*)(Ab1);
    float4 pb0 = *(const float4*)(Bb0);
    float4 pb1 = *(const float4*)(Bb1);

    float acc[8][8];
    #pragma unroll
    for (int i = 0; i < 8; i++)
        #pragma unroll
        for (int j = 0; j < 8; j++) acc[i][j] = 0.f;

    for (int k0 = 0; k0 < K; k0 += 16) {
        As[aCol + 0][aRow]      = pa0.x;
        As[aCol + 1][aRow]      = pa0.y;
        As[aCol + 2][aRow]      = pa0.z;
        As[aCol + 3][aRow]      = pa0.w;
        As[aCol + 0][aRow + 64] = pa1.x;
        As[aCol + 1][aRow + 64] = pa1.y;
        As[aCol + 2][aRow + 64] = pa1.z;
        As[aCol + 3][aRow + 64] = pa1.w;
        *(float4*)&Bs[bRow][bCol]     = pb0;
        *(float4*)&Bs[bRow + 8][bCol] = pb1;
        __syncthreads();

        if (k0 + 16 < K) {  // prefetch next tile into registers
            pa0 = *(const float4*)(Ab0 + k0 + 16);
            pa1 = *(const float4*)(Ab1 + k0 + 16);
            pb0 = *(const float4*)(Bb0 + (long)(k0 + 16) * ldb);
            pb1 = *(const float4*)(Bb1 + (long)(k0 + 16) * ldb);
        }

        #pragma unroll
        for (int k = 0; k < 16; k++) {
            float a_frag[8], b_frag[8];
            *(float4*)&a_frag[0] = *(const float4*)&As[k][ty * 4];
            *(float4*)&a_frag[4] = *(const float4*)&As[k][64 + ty * 4];
            *(float4*)&b_frag[0] = *(const float4*)&Bs[k][tx * 4];
            *(float4*)&b_frag[4] = *(const float4*)&Bs[k][64 + tx * 4];
            #pragma unroll
            for (int i = 0; i < 8; i++)
                #pragma unroll
                for (int j = 0; j < 8; j++)
                    acc[i][j] += a_frag[i] * b_frag[j];
        }
        __syncthreads();
    }

    // epilogue
    float bcol[8];
    #pragma unroll
    for (int j = 0; j < 4; j++) {
        bcol[j]     = bias ? bias[bn + tx * 4 + j] : 0.f;
        bcol[j + 4] = bias ? bias[bn + 64 + tx * 4 + j] : 0.f;
    }
    #pragma unroll
    for (int ih = 0; ih < 2; ih++) {
        #pragma unroll
        for (int i = 0; i < 4; i++) {
            long row = bm + ih * 64 + ty * 4 + i;
            float* crow = C + row * (long)ldc + bn;
            #pragma unroll
            for (int jh = 0; jh < 2; jh++) {
                float4 v;
                v.x = acc[ih * 4 + i][jh * 4 + 0] + bcol[jh * 4 + 0];
                v.y = acc[ih * 4 + i][jh * 4 + 1] + bcol[jh * 4 + 1];
                v.z = acc[ih * 4 + i][jh * 4 + 2] + bcol[jh * 4 + 2];
                v.w = acc[ih * 4 + i][jh * 4 + 3] + bcol[jh * 4 + 3];
                if (doRelu) {
                    v.x = fmaxf(v.x, 0.f); v.y = fmaxf(v.y, 0.f);
                    v.z = fmaxf(v.z, 0.f); v.w = fmaxf(v.w, 0.f);
                }
                *(float4*)(crow + jh * 64 + tx * 4) = v;
            }
        }
    }
}

// --------------------- H1 assembly: relu(Atop[j]+Bbot[i]+bg1) ---------------
// rows 0..32767:  ctx pairs (b,i,j) -> Atop[b*16+j] + Bbot[b*16+i]
// rows 32768..65535: cc pairs (b,a,j) -> Atop[b*16+j] + Bbot[b*16+8+a]
__global__ void assemble_h1_kernel(float* __restrict__ H1) {
    int row = blockIdx.x;
    int n4  = threadIdx.x;             // 0..263
    int b, islot, jslot;
    if (row < 32768) {
        b = row >> 6; int rem = row & 63; islot = rem >> 3; jslot = rem & 7;
    } else {
        int r = row - 32768; b = r >> 6; islot = 8 + ((r >> 3) & 7); jslot = r & 7;
    }
    const float4* av = (const float4*)(g_Atop + (size_t)(b * 16 + jslot) * NP);
    const float4* bv = (const float4*)(g_Bbot + (size_t)(b * 16 + islot) * NP);
    const float4* gv = (const float4*)g_bg1p;
    float4 x = av[n4], y = bv[n4], g = gv[n4], o;
    o.x = fmaxf(x.x + y.x + g.x, 0.f);
    o.y = fmaxf(x.y + y.y + g.y, 0.f);
    o.z = fmaxf(x.z + y.z + g.z, 0.f);
    o.w = fmaxf(x.w + y.w + g.w, 0.f);
    ((float4*)(H1 + (size_t)row * NP))[n4] = o;
}

// ctx_sum[b] = sum over 64 ctx-pair rows of H3
__global__ void ctx_sum_kernel(const float* __restrict__ H3) {
    int b = blockIdx.x;                // 0..511
    int n4 = threadIdx.x;              // 0..263
    const float4* base = (const float4*)(H3 + (size_t)b * 64 * NP);
    float4 s = make_float4(0.f, 0.f, 0.f, 0.f);
    #pragma unroll 4
    for (int p = 0; p < 64; p++) {
        float4 v = base[p * NP4 + n4];
        s.x += v.x; s.y += v.y; s.z += v.z; s.w += v.w;
    }
    ((float4*)(g_ctxsum + (size_t)b * NP))[n4] = s;
}

// rel[b*8+a] = ctx_sum[b] + sum_j H3cc[b,a,j]
__global__ void relations_kernel(const float* __restrict__ H3) {
    int r = blockIdx.x;                // 0..4095
    int b = r >> 3, a = r & 7;
    int n4 = threadIdx.x;
    const float4* base =
        (const float4*)(H3 + (size_t)(32768 + b * 64 + a * 8) * NP);
    float4 s = ((const float4*)(g_ctxsum + (size_t)b * NP))[n4];
    #pragma unroll
    for (int j = 0; j < 8; j++) {
        float4 v = base[j * NP4 + n4];
        s.x += v.x; s.y += v.y; s.z += v.z; s.w += v.w;
    }
    ((float4*)(g_rel + (size_t)r * NP))[n4] = s;
}

// f_out[r] = H4[r,:] . Wf2 + bf2  (warp per row)
__global__ void fout_kernel(const float* __restrict__ Wf2,
                            const float* __restrict__ bf2) {
    int r = blockIdx.x * 8 + (threadIdx.x >> 5);
    int lane = threadIdx.x & 31;
    const float* h = g_H4 + (size_t)r * NP;
    float s = 0.f;
    for (int k = lane; k < T_DIM; k += 32) s += h[k] * Wf2[k];
    #pragma unroll
    for (int o = 16; o > 0; o >>= 1) s += __shfl_down_sync(0xffffffffu, s, o);
    if (lane == 0) g_fout[r] = s + bf2[0];
}

// final: BCE loss (mean over 4096) + accuracy (mean over 512)
__global__ void final_kernel(const int* __restrict__ labels,
                             float* __restrict__ out, int out_size) {
    __shared__ float sloss[512];
    __shared__ float sacc[512];
    int b = threadIdx.x;               // 0..511
    int lab = labels[b];
    float lsum = 0.f;
    float best = 0.f;
    int arg = 0;
    #pragma unroll
    for (int a = 0; a < 8; a++) {
        float f = g_fout[b * 8 + a];
        lsum += fmaxf(f, 0.f) - f * (a == lab ? 1.f : 0.f)
                + log1pf(expf(-fabsf(f)));
        if (a == 0 || f > best) { best = f; arg = a; }
    }
    sloss[b] = lsum;
    sacc[b] = (arg == lab) ? 1.f : 0.f;
    __syncthreads();
    for (int stride = 256; stride > 0; stride >>= 1) {
        if (b < stride) {
            sloss[b] += sloss[b + stride];
            sacc[b]  += sacc[b + stride];
        }
        __syncthreads();
    }
    if (b == 0) {
        out[0] = sloss[0] / 4096.f;
        if (out_size >= 2) out[1] = sacc[0] / 512.f;
    }
}

// ------------------------------- host launch --------------------------------
static inline float* sym(const void* s) {
    void* p = nullptr;
    cudaGetSymbolAddress(&p, s);
    return (float*)p;
}

extern "C" void kernel_launch(void* const* d_in, const int* in_sizes, int n_in,
                              void* d_out, int out_size) {
    const float* x      = (const float*)d_in[0];
    const float* W_emb  = (const float*)d_in[1];
    const float* b_emb  = (const float*)d_in[2];
    const float* Wg1    = (const float*)d_in[3];
    const float* bg1    = (const float*)d_in[4];
    const float* Wg2    = (const float*)d_in[5];
    const float* bg2    = (const float*)d_in[6];
    const float* Wg3    = (const float*)d_in[7];
    const float* bg3    = (const float*)d_in[8];
    const float* Wf1    = (const float*)d_in[9];
    const float* bf1    = (const float*)d_in[10];
    const float* Wf2    = (const float*)d_in[11];
    const float* bf2    = (const float*)d_in[12];
    const int*   labels = (const int*)d_in[13];
    float* out = (float*)d_out;

    float* tagged = sym(g_tagged);
    float* w1t = sym(g_W1top);
    float* w1b = sym(g_W1bot);
    float* w2p = sym(g_W2p);
    float* w3p = sym(g_W3p);
    float* wf1p = sym(g_Wf1p);
    float* bg1p = sym(g_bg1p);
    float* bg2p = sym(g_bg2p);
    float* bg3p = sym(g_bg3p);
    float* bf1p = sym(g_bf1p);
    float* atop = sym(g_Atop);
    float* bbot = sym(g_Bbot);
    float* ha = sym(g_HA);
    float* hb = sym(g_HB);
    float* rel = sym(g_rel);
    float* h4 = sym(g_H4);

    // ---- weight/bias padding (cheap, ~25 MB of copies) ----
    {
        long n1 = (long)KP1 * NP;
        long n2 = (long)KP2 * NP;
        int tb = 256;
        pad_weight_kernel<<<(unsigned)((n1 + tb - 1) / tb), tb>>>(w1t, Wg1, KP1, D_TAG, 0);
        pad_weight_kernel<<<(unsigned)((n1 + tb - 1) / tb), tb>>>(w1b, Wg1, KP1, D_TAG, D_TAG);
        pad_weight_kernel<<<(unsigned)((n2 + tb - 1) / tb), tb>>>(w2p, Wg2, KP2, T_DIM, 0);
        pad_weight_kernel<<<(unsigned)((n2 + tb - 1) / tb), tb>>>(w3p, Wg3, KP2, T_DIM, 0);
        pad_weight_kernel<<<(unsigned)((n2 + tb - 1) / tb), tb>>>(wf1p, Wf1, KP2, T_DIM, 0);
        pad_bias_kernel<<<9, 128>>>(bg1p, bg1);
        pad_bias_kernel<<<9, 128>>>(bg2p, bg2);
        pad_bias_kernel<<<9, 128>>>(bg3p, bg3);
        pad_bias_kernel<<<9, 128>>>(bf1p, bf1);
    }

    // ---- embedding: tagged[:, :512] = x(8192,6400) @ W_emb + b_emb ----
    {
        dim3 grid(D_EMB / 128, NROWS_EMB / 128);
        sgemm_kernel<<<grid, 256>>>(x, 6400, W_emb, D_EMB, tagged, KP1,
                                    6400, b_emb, 0);
    }
    tag_kernel<<<NROWS_EMB, 32>>>(tagged);

    // ---- layer-1 factored GEMMs over all 16 slots ----
    {
        dim3 grid(NP / 128, NROWS_EMB / 128);
        sgemm_kernel<<<grid, 256>>>(tagged, KP1, w1t, NP, atop, NP,
                                    KP1, nullptr, 0);
        sgemm_kernel<<<grid, 256>>>(tagged, KP1, w1b, NP, bbot, NP,
                                    KP1, nullptr, 0);
    }

    // ---- H1 = relu(Atop[j] + Bbot[i] + bg1) for all 65536 pairs ----
    assemble_h1_kernel<<<H_ROWS, NV4>>>(ha);

    // ---- layers 2 and 3 ----
    {
        dim3 grid(NP / 128, H_ROWS / 128);
        sgemm_kernel<<<grid, 256>>>(ha, NP, w2p, NP, hb, NP, KP2, bg2p, 1);
        sgemm_kernel<<<grid, 256>>>(hb, NP, w3p, NP, ha, NP, KP2, bg3p, 1);
    }

    // ---- reductions -> relations ----
    ctx_sum_kernel<<<BATCH, NV4>>>(ha);
    relations_kernel<<<BATCH * 8, NV4>>>(ha);

    // ---- f layer ----
    {
        dim3 grid(NP / 128, (BATCH * 8) / 128);
        sgemm_kernel<<<grid, 256>>>(rel, NP, wf1p, NP, h4, NP, KP2, bf1p, 1);
    }
    fout_kernel<<<BATCH, 256>>>(Wf2, bf2);

    // ---- loss + acc ----
    final_kernel<<<1, 512>>>(labels, out, out_size);
}